// round 2
// baseline (speedup 1.0000x reference)
#include <cuda_runtime.h>
#include <cstdint>

// ---------------------------------------------------------------------------
// Sparse (occupancy-masked) 3D U-Net, grid 96^3, NF=16.
// Strategy: compact active voxel lists per level, compute only active outputs.
// All intermediate activations live in zero-initialized __device__ globals;
// only active voxels are ever written, so off-mask values stay exactly 0.
// ---------------------------------------------------------------------------

#define G0 96
#define G1 48
#define G2 24
#define NV0 (G0*G0*G0)   // 884736
#define NV1 (G1*G1*G1)   // 110592
#define NV2 (G2*G2*G2)   // 13824
#define NB0 (NV0/128)    // 6912
#define NB1 (NV1/128)    // 864
#define NB2 (NV2/128)    // 108

// Scratch (zero-initialized at module load; only active voxels written)
__device__ float g_XM [NV0];
__device__ float g_S0 [16*NV0];
__device__ float g_S1 [16*NV0];
__device__ float g_S2 [32*NV0];
__device__ float g_L1a[32*NV1];
__device__ float g_L1b[32*NV1];
__device__ float g_L1c[32*NV1];
__device__ float g_L1d[64*NV1];
__device__ float g_L2a[64*NV2];
__device__ float g_L2b[64*NV2];
__device__ float g_L2c[64*NV2];
__device__ float g_M1 [NV1];
__device__ float g_M2 [NV2];
__device__ int   g_LIST0[NV0];
__device__ int   g_LIST1[NV1];
__device__ int   g_LIST2[NV2];
__device__ int   g_CNT[4];

// ---------------------------------------------------------------------------
__global__ void k_mask_input(const float* __restrict__ x,
                             const float* __restrict__ occ,
                             float* __restrict__ xm, int n)
{
    int v = blockIdx.x * blockDim.x + threadIdx.x;
    if (v < n) xm[v] = x[v] * occ[v];
}

__global__ void k_reset(int* cnt)
{
    if (threadIdx.x < 4) cnt[threadIdx.x] = 0;
}

__global__ void k_compact(const float* __restrict__ m, int n,
                          int* __restrict__ list, int* __restrict__ cnt)
{
    int v = blockIdx.x * blockDim.x + threadIdx.x;
    if (v < n && m[v] != 0.f) {
        int p = atomicAdd(cnt, 1);
        list[p] = v;
    }
}

__global__ void k_maxpool(const float* __restrict__ in,
                          float* __restrict__ out, int gout)
{
    int v = blockIdx.x * blockDim.x + threadIdx.x;
    int n = gout * gout * gout;
    if (v >= n) return;
    int gin = gout * 2;
    int z = v / (gout * gout);
    int y = (v / gout) % gout;
    int x = v % gout;
    float mx = 0.f;
    #pragma unroll
    for (int a = 0; a < 2; a++)
        #pragma unroll
        for (int b = 0; b < 2; b++)
            #pragma unroll
            for (int c = 0; c < 2; c++)
                mx = fmaxf(mx, in[((size_t)(2*z+a)*gin + (2*y+b))*gin + (2*x+c)]);
    out[v] = mx;
}

// ---------------------------------------------------------------------------
// Sparse 3x3x3 SAME conv over an active-voxel list. Supports implicit concat
// of two input tensors (CIN1 channels from in1, CIN2 from in2).
// blockIdx.y selects a block of COB output channels (co0 = blockIdx.y*COB).
// Weight OIDHW: w[((co)*CIN + ci)*27 + (kd*9+kh*3+kw)], cross-correlation.
// ---------------------------------------------------------------------------
template<int CIN1, int CIN2, int COB, bool RELU, int CHUNK>
__launch_bounds__(128)
__global__ void conv3s(const float* __restrict__ in1, const float* __restrict__ in2,
                       const float* __restrict__ wgl, const int* __restrict__ list,
                       const int* __restrict__ cntp, float* __restrict__ out,
                       int g, int nv)
{
    constexpr int CIN = CIN1 + CIN2;
    const int cnt = *cntp;
    if (blockIdx.x * 128 >= cnt) return;

    __shared__ float wsh[CHUNK * 27 * COB];
    const int co0 = blockIdx.y * COB;
    const int t   = blockIdx.x * 128 + threadIdx.x;
    const bool act = t < cnt;
    const int v = act ? list[t] : list[0];
    const int gg = g * g;
    const int z = v / gg;
    const int y = (v / g) % g;
    const int x = v % g;

    float acc[COB];
    #pragma unroll
    for (int co = 0; co < COB; co++) acc[co] = 0.f;

    for (int ci0 = 0; ci0 < CIN; ci0 += CHUNK) {
        __syncthreads();
        for (int i = threadIdx.x; i < CHUNK * 27 * COB; i += 128) {
            int cil = i / (27 * COB);
            int rem = i - cil * (27 * COB);
            int tap = rem / COB;
            int co  = rem - tap * COB;
            int ci  = ci0 + cil;
            wsh[i] = (ci < CIN) ? wgl[((size_t)(co0 + co) * CIN + ci) * 27 + tap] : 0.f;
        }
        __syncthreads();

        #pragma unroll 1
        for (int cil = 0; cil < CHUNK; cil++) {
            int ci = ci0 + cil;
            if (ci >= CIN) break;
            const float* src = (ci < CIN1) ? (in1 + (size_t)ci * nv)
                                           : (in2 + (size_t)(ci - CIN1) * nv);
            #pragma unroll
            for (int dz = -1; dz <= 1; dz++) {
                int zz = z + dz;
                if ((unsigned)zz >= (unsigned)g) continue;
                #pragma unroll
                for (int dy = -1; dy <= 1; dy++) {
                    int yy = y + dy;
                    if ((unsigned)yy >= (unsigned)g) continue;
                    const float* row = src + ((size_t)zz * g + yy) * g;
                    #pragma unroll
                    for (int dx = -1; dx <= 1; dx++) {
                        int xx = x + dx;
                        if ((unsigned)xx >= (unsigned)g) continue;
                        float val = __ldg(row + xx);
                        int tap = (dz + 1) * 9 + (dy + 1) * 3 + (dx + 1);
                        const float* wp = &wsh[(cil * 27 + tap) * COB];
                        #pragma unroll
                        for (int co = 0; co < COB; co++)
                            acc[co] += val * wp[co];
                    }
                }
            }
        }
    }

    if (act) {
        #pragma unroll
        for (int co = 0; co < COB; co++) {
            float r = acc[co];
            if (RELU) r = fmaxf(r, 0.f);
            out[(size_t)(co0 + co) * nv + v] = r;
        }
    }
}

// ---------------------------------------------------------------------------
// Sparse stride-2 k=2 VALID conv (downsample). Output voxels = coarse list.
// y[o,d,h,w] = sum_i sum_{k in 2^3} x[i,2d+kd,2h+kh,2w+kw] * w[o,i,kd,kh,kw]
// ---------------------------------------------------------------------------
template<int CIN, int COB>
__launch_bounds__(128)
__global__ void down2s(const float* __restrict__ in, const float* __restrict__ wgl,
                       const int* __restrict__ list, const int* __restrict__ cntp,
                       float* __restrict__ out, int gout, int nvin, int nvout)
{
    const int cnt = *cntp;
    if (blockIdx.x * 128 >= cnt) return;

    __shared__ float wsh[CIN * 8 * COB];
    const int co0 = blockIdx.y * COB;
    for (int i = threadIdx.x; i < CIN * 8 * COB; i += 128) {
        int ci  = i / (8 * COB);
        int rem = i - ci * (8 * COB);
        int tap = rem / COB;
        int co  = rem - tap * COB;
        wsh[i] = wgl[((size_t)(co0 + co) * CIN + ci) * 8 + tap];
    }
    __syncthreads();

    const int t = blockIdx.x * 128 + threadIdx.x;
    const bool act = t < cnt;
    const int v = act ? list[t] : list[0];
    const int z = v / (gout * gout);
    const int y = (v / gout) % gout;
    const int x = v % gout;
    const int gin = gout * 2;

    float acc[COB];
    #pragma unroll
    for (int co = 0; co < COB; co++) acc[co] = 0.f;

    #pragma unroll 2
    for (int ci = 0; ci < CIN; ci++) {
        const float* src = in + (size_t)ci * nvin;
        #pragma unroll
        for (int kd = 0; kd < 2; kd++)
            #pragma unroll
            for (int kh = 0; kh < 2; kh++)
                #pragma unroll
                for (int kw = 0; kw < 2; kw++) {
                    float val = __ldg(src + ((size_t)(2*z+kd)*gin + (2*y+kh))*gin + (2*x+kw));
                    const float* wp = &wsh[(ci * 8 + (kd*4 + kh*2 + kw)) * COB];
                    #pragma unroll
                    for (int co = 0; co < COB; co++)
                        acc[co] += val * wp[co];
                }
    }

    if (act) {
        #pragma unroll
        for (int co = 0; co < COB; co++)
            out[(size_t)(co0 + co) * nvout + v] = acc[co];
    }
}

// ---------------------------------------------------------------------------
// Sparse k=2 s=2 VALID transpose conv (upsample). Output voxels = fine list.
// jax.lax.conv_transpose (no kernel flip, pad (1,1), lhs_dilation 2) gives:
//   y[o, 2m+a, 2n+b, 2p+c] = sum_i x[i,m,n,p] * w[o,i,1-a,1-b,1-c]
// ---------------------------------------------------------------------------
template<int CIN, int COB>
__launch_bounds__(128)
__global__ void up2s(const float* __restrict__ in, const float* __restrict__ wgl,
                     const int* __restrict__ list, const int* __restrict__ cntp,
                     float* __restrict__ out, int gout, int nvin, int nvout)
{
    const int cnt = *cntp;
    if (blockIdx.x * 128 >= cnt) return;

    __shared__ float wsh[CIN * 8 * COB];
    const int co0 = blockIdx.y * COB;
    for (int i = threadIdx.x; i < CIN * 8 * COB; i += 128) {
        int ci  = i / (8 * COB);
        int rem = i - ci * (8 * COB);
        int tap = rem / COB;
        int co  = rem - tap * COB;
        wsh[i] = wgl[((size_t)(co0 + co) * CIN + ci) * 8 + tap];
    }
    __syncthreads();

    const int t = blockIdx.x * 128 + threadIdx.x;
    const bool act = t < cnt;
    const int v = act ? list[t] : list[0];
    const int z = v / (gout * gout);
    const int y = (v / gout) % gout;
    const int x = v % gout;
    const int gin = gout >> 1;
    const int p = ((size_t)0, ((z >> 1) * gin + (y >> 1)) * gin + (x >> 1));
    const int tap = (1 - (z & 1)) * 4 + (1 - (y & 1)) * 2 + (1 - (x & 1));

    float acc[COB];
    #pragma unroll
    for (int co = 0; co < COB; co++) acc[co] = 0.f;

    #pragma unroll 4
    for (int ci = 0; ci < CIN; ci++) {
        float val = __ldg(in + (size_t)ci * nvin + p);
        const float* wp = &wsh[(ci * 8 + tap) * COB];
        #pragma unroll
        for (int co = 0; co < COB; co++)
            acc[co] += val * wp[co];
    }

    if (act) {
        #pragma unroll
        for (int co = 0; co < COB; co++)
            out[(size_t)(co0 + co) * nvout + v] = acc[co];
    }
}

// ---------------------------------------------------------------------------
extern "C" void kernel_launch(void* const* d_in, const int* in_sizes, int n_in,
                              void* d_out, int out_size)
{
    const float* x      = (const float*)d_in[0];
    const float* occ    = (const float*)d_in[1];
    const float* w_in   = (const float*)d_in[2];
    const float* w_e0d  = (const float*)d_in[3];
    const float* w_e0a  = (const float*)d_in[4];
    const float* w_e0b  = (const float*)d_in[5];
    const float* w_e1d  = (const float*)d_in[6];
    const float* w_e1a  = (const float*)d_in[7];
    const float* w_e1b  = (const float*)d_in[8];
    const float* w_d0u  = (const float*)d_in[9];
    const float* w_d0a  = (const float*)d_in[10];
    const float* w_d0b  = (const float*)d_in[11];
    const float* w_d1u  = (const float*)d_in[12];
    const float* w_d1a  = (const float*)d_in[13];
    const float* w_d1b  = (const float*)d_in[14];
    const float* w_oa   = (const float*)d_in[15];
    const float* w_ob   = (const float*)d_in[16];

    float *XM, *S0, *S1, *S2, *L1a, *L1b, *L1c, *L1d, *L2a, *L2b, *L2c, *M1, *M2;
    int *LIST0, *LIST1, *LIST2, *CNT;
    cudaGetSymbolAddress((void**)&XM,  g_XM);
    cudaGetSymbolAddress((void**)&S0,  g_S0);
    cudaGetSymbolAddress((void**)&S1,  g_S1);
    cudaGetSymbolAddress((void**)&S2,  g_S2);
    cudaGetSymbolAddress((void**)&L1a, g_L1a);
    cudaGetSymbolAddress((void**)&L1b, g_L1b);
    cudaGetSymbolAddress((void**)&L1c, g_L1c);
    cudaGetSymbolAddress((void**)&L1d, g_L1d);
    cudaGetSymbolAddress((void**)&L2a, g_L2a);
    cudaGetSymbolAddress((void**)&L2b, g_L2b);
    cudaGetSymbolAddress((void**)&L2c, g_L2c);
    cudaGetSymbolAddress((void**)&M1,  g_M1);
    cudaGetSymbolAddress((void**)&M2,  g_M2);
    cudaGetSymbolAddress((void**)&LIST0, g_LIST0);
    cudaGetSymbolAddress((void**)&LIST1, g_LIST1);
    cudaGetSymbolAddress((void**)&LIST2, g_LIST2);
    cudaGetSymbolAddress((void**)&CNT,   g_CNT);

    float* OUT = (float*)d_out;

    // Masks + compaction
    k_mask_input<<<NB0, 128>>>(x, occ, XM, NV0);
    k_reset<<<1, 32>>>(CNT);
    k_compact<<<NB0, 128>>>(occ, NV0, LIST0, CNT + 0);
    k_maxpool<<<NB1, 128>>>(occ, M1, G1);
    k_compact<<<NB1, 128>>>(M1, NV1, LIST1, CNT + 1);
    k_maxpool<<<NB2, 128>>>(M1, M2, G2);
    k_compact<<<NB2, 128>>>(M2, NV2, LIST2, CNT + 2);

    // input block: conv3 1->16 @96^3
    conv3s<1, 0, 16, false, 8><<<dim3(NB0, 1), 128>>>(XM, (const float*)nullptr, w_in, LIST0, CNT + 0, S0, G0, NV0);

    // encoder level 0
    down2s<16, 32><<<dim3(NB1, 1), 128>>>(S0, w_e0d, LIST1, CNT + 1, L1a, G1, NV0, NV1);
    conv3s<32, 0, 32, true,  8><<<dim3(NB1, 1), 128>>>(L1a, (const float*)nullptr, w_e0a, LIST1, CNT + 1, L1b, G1, NV1);
    conv3s<32, 0, 32, false, 8><<<dim3(NB1, 1), 128>>>(L1b, (const float*)nullptr, w_e0b, LIST1, CNT + 1, L1c, G1, NV1); // skip1

    // encoder level 1
    down2s<32, 32><<<dim3(NB2, 2), 128>>>(L1c, w_e1d, LIST2, CNT + 2, L2a, G2, NV1, NV2);
    conv3s<64, 0, 32, true,  8><<<dim3(NB2, 2), 128>>>(L2a, (const float*)nullptr, w_e1a, LIST2, CNT + 2, L2b, G2, NV2);
    conv3s<64, 0, 32, false, 8><<<dim3(NB2, 2), 128>>>(L2b, (const float*)nullptr, w_e1b, LIST2, CNT + 2, L2c, G2, NV2);

    // decoder stage 0 (back to level 1)
    up2s<64, 16><<<dim3(NB1, 2), 128>>>(L2c, w_d0u, LIST1, CNT + 1, L1a, G1, NV2, NV1);
    conv3s<32, 32, 32, true, 8><<<dim3(NB1, 2), 128>>>(L1a, L1c, w_d0a, LIST1, CNT + 1, L1d, G1, NV1); // concat(up, skip1) 64->64
    conv3s<64, 0, 32, false, 8><<<dim3(NB1, 1), 128>>>(L1d, (const float*)nullptr, w_d0b, LIST1, CNT + 1, L1b, G1, NV1); // 64->32

    // decoder stage 1 (back to level 0)
    up2s<32, 16><<<dim3(NB0, 1), 128>>>(L1b, w_d1u, LIST0, CNT + 0, S1, G0, NV1, NV0);
    conv3s<16, 16, 32, true, 8><<<dim3(NB0, 1), 128>>>(S1, S0, w_d1a, LIST0, CNT + 0, S2, G0, NV0); // concat(up, skip0) 32->32
    conv3s<32, 0, 16, false, 8><<<dim3(NB0, 1), 128>>>(S2, (const float*)nullptr, w_d1b, LIST0, CNT + 0, S1, G0, NV0); // 32->16

    // output block
    conv3s<16, 0, 16, true, 8><<<dim3(NB0, 1), 128>>>(S1, (const float*)nullptr, w_oa, LIST0, CNT + 0, S0, G0, NV0);
    cudaMemsetAsync(d_out, 0, (size_t)out_size * sizeof(float));
    conv3s<16, 0, 5, false, 8><<<dim3(NB0, 1), 128>>>(S0, (const float*)nullptr, w_ob, LIST0, CNT + 0, OUT, G0, NV0);
}